// round 17
// baseline (speedup 1.0000x reference)
#include <cuda_runtime.h>

// out[i] = in[i,1] + w*(in[i,0]-in[i,1]).  N = 16777216, pure streaming.
// Champion shape (kernel 26.21us, DRAM 78.9%, HBM 6.25 TB/s): 4 outputs/
// thread, two adjacent __ldg LDG.128, __stcs STG.128.
// Single delta: block 128 -> 64 (65536 blocks). Granularity trend so far:
// 512 worse < 256 ~= 128 best-occ; test the finer end. 2 warps/CTA x 32
// CTA/SM = 64 warps = full warp cap, so occupancy ceiling is preserved.

__global__ __launch_bounds__(64)
void skip_kernel(const float4* __restrict__ in,
                 const float* __restrict__ w_ptr,
                 float4* __restrict__ out)
{
    const unsigned i = blockIdx.x * blockDim.x + threadIdx.x;
    const float w = __ldg(w_ptr);

    float4 a = __ldg(&in[2u * i]);
    float4 b = __ldg(&in[2u * i + 1u]);

    float4 o;
    o.x = fmaf(w, a.x - a.y, a.y);
    o.y = fmaf(w, a.z - a.w, a.w);
    o.z = fmaf(w, b.x - b.y, b.y);
    o.w = fmaf(w, b.z - b.w, b.w);

    __stcs(&out[i], o);
}

extern "C" void kernel_launch(void* const* d_in, const int* in_sizes, int n_in,
                              void* d_out, int out_size)
{
    const float* input  = (const float*)d_in[0];   // [N,2]
    const float* weight = (const float*)d_in[1];   // [1,1]
    float*       out    = (float*)d_out;           // [N,1]

    const int n = in_sizes[0] / 2;     // 16777216 outputs
    const int n4 = n / 4;              // 4 outputs per thread, exact
    const int threads = 64;
    const int blocks = n4 / threads;   // 65536

    skip_kernel<<<blocks, threads>>>((const float4*)input, weight, (float4*)out);
}